// round 15
// baseline (speedup 1.0000x reference)
#include <cuda_runtime.h>
#include <cuda_fp16.h>

// Problem dims (fixed by reference setup_inputs)
constexpr int B_ = 8;
constexpr int T_ = 100;
constexpr int S_ = 400;
constexpr int H_ = 256;

constexpr int TGT = 2;    // t-rows per attn CTA
constexpr int NTH = 416;  // attn threads (13 warps; 400 active s-lanes)

// Scratch (device globals — no allocation allowed)
__device__ float g_WhT[B_ * H_ * S_];   // (enc @ W_h + b_attn)^T : [b][h][s]
__device__ float g_Ws [B_ * T_ * H_];   // dec @ W_s
__device__ float g_Apre[B_ * T_ * S_];  // A_prelim

// Packed tanh: one MUFU evaluates tanh for both t-rows. Inputs/accum stay f32.
__device__ __forceinline__ unsigned tanh2(unsigned x) {
    unsigned y;
    asm("tanh.approx.f16x2 %0, %1;" : "=r"(y) : "r"(x));
    return y;
}

// ---------------------------------------------------------------------------
// Fused projection GEMMs, 64x32 tiles, 256 thr, 2x4 per thread.
// SMEM double-buffered: one __syncthreads per k-chunk, LDG issued early.
// blockIdx.y <  50 : WhT tile -> transposed store into g_WhT (+bias)
// blockIdx.y >= 50 : Ws  tile -> row-major store into g_Ws
// ---------------------------------------------------------------------------
__global__ __launch_bounds__(256) void dual_gemm(
    const float* __restrict__ enc, const float* __restrict__ W_h,
    const float* __restrict__ dec, const float* __restrict__ W_s,
    const float* __restrict__ bias)
{
    constexpr int K = H_, N = H_;
    bool isWh = blockIdx.y < 50;
    int  myTile = isWh ? blockIdx.y : (blockIdx.y - 50);
    int  M  = isWh ? B_ * S_ : B_ * T_;
    const float* A  = isWh ? enc : dec;
    const float* Bm = isWh ? W_h : W_s;

    int m0 = myTile * 64, n0 = blockIdx.x * 32;
    int tid = threadIdx.x;
    int tx = tid & 7;
    int ty = tid >> 3;

    __shared__ float As[2][16][68];
    __shared__ float Bs[2][16][36];
    __shared__ float Ts[32][65];

    float acc[2][4] = {};

    int lm  = tid >> 2;
    int lk4 = tid & 3;
    int bkr = tid >> 4;
    int bnc = tid & 15;

    // prologue: chunk 0 -> buffer 0
    {
        float4 av = make_float4(0.f, 0.f, 0.f, 0.f);
        int gm = m0 + lm;
        if (gm < M) av = *(const float4*)(A + (size_t)gm * K + lk4 * 4);
        As[0][lk4 * 4 + 0][lm] = av.x;
        As[0][lk4 * 4 + 1][lm] = av.y;
        As[0][lk4 * 4 + 2][lm] = av.z;
        As[0][lk4 * 4 + 3][lm] = av.w;
        float2 bv = *(const float2*)(Bm + (size_t)bkr * N + n0 + bnc * 2);
        Bs[0][bkr][bnc * 2 + 0] = bv.x;
        Bs[0][bkr][bnc * 2 + 1] = bv.y;
    }
    __syncthreads();

    int buf = 0;
    for (int k = 0; k < K; k += 16) {
        bool hasNext = (k + 16 < K);
        float4 av2 = make_float4(0.f, 0.f, 0.f, 0.f);
        float2 bv2 = make_float2(0.f, 0.f);
        if (hasNext) {
            int gm = m0 + lm;
            if (gm < M) av2 = *(const float4*)(A + (size_t)gm * K + k + 16 + lk4 * 4);
            bv2 = *(const float2*)(Bm + (size_t)(k + 16 + bkr) * N + n0 + bnc * 2);
        }
#pragma unroll
        for (int kk = 0; kk < 16; kk++) {
            float2 a = *(float2*)&As[buf][kk][ty * 2];
            float4 b = *(float4*)&Bs[buf][kk][tx * 4];
            acc[0][0] = fmaf(a.x, b.x, acc[0][0]);
            acc[0][1] = fmaf(a.x, b.y, acc[0][1]);
            acc[0][2] = fmaf(a.x, b.z, acc[0][2]);
            acc[0][3] = fmaf(a.x, b.w, acc[0][3]);
            acc[1][0] = fmaf(a.y, b.x, acc[1][0]);
            acc[1][1] = fmaf(a.y, b.y, acc[1][1]);
            acc[1][2] = fmaf(a.y, b.z, acc[1][2]);
            acc[1][3] = fmaf(a.y, b.w, acc[1][3]);
        }
        if (hasNext) {
            int nb = buf ^ 1;
            As[nb][lk4 * 4 + 0][lm] = av2.x;
            As[nb][lk4 * 4 + 1][lm] = av2.y;
            As[nb][lk4 * 4 + 2][lm] = av2.z;
            As[nb][lk4 * 4 + 3][lm] = av2.w;
            Bs[nb][bkr][bnc * 2 + 0] = bv2.x;
            Bs[nb][bkr][bnc * 2 + 1] = bv2.y;
            __syncthreads();
            buf = nb;
        }
    }

    if (isWh) {
        __syncthreads();  // protect Ts vs in-flight As/Bs reads
#pragma unroll
        for (int j = 0; j < 4; j++) {
            float bi = bias[n0 + tx * 4 + j];
#pragma unroll
            for (int i = 0; i < 2; i++)
                Ts[tx * 4 + j][ty * 2 + i] = acc[i][j] + bi;
        }
        __syncthreads();
#pragma unroll
        for (int kk = 0; kk < 8; kk++) {
            int e  = tid + 256 * kk;
            int h  = e >> 6;
            int sl = e & 63;
            int m  = m0 + sl;
            int b  = m / S_;
            int s  = m - b * S_;
            g_WhT[(size_t)b * H_ * S_ + (size_t)(n0 + h) * S_ + s] = Ts[h][sl];
        }
    } else {
#pragma unroll
        for (int i = 0; i < 2; i++) {
            int gm = m0 + ty * 2 + i;
            if (gm < M) {
#pragma unroll
                for (int j = 0; j < 4; j++)
                    g_Ws[(size_t)gm * N + n0 + tx * 4 + j] = acc[i][j];
            }
        }
    }
}

// ---------------------------------------------------------------------------
// Context GEMM, split-K(4): blockIdx.z = b*4 + ks. K slices 112/96/96/96.
// 64x32 tiles, 2x4 per thread, double-buffered; partials combined via
// atomicAdd (ctx is zeroed by attn_pass<false>).
// ---------------------------------------------------------------------------
__global__ __launch_bounds__(256) void gemm_ctx(
    const float* __restrict__ Ain, const float* __restrict__ Bin,
    float* __restrict__ Cout, int M, int N, int Kfull,
    long long sA, long long sB, long long sC)
{
    int bz = blockIdx.z >> 2;
    int ks = blockIdx.z & 3;
    int kOff = (ks == 0) ? 0 : (112 + (ks - 1) * 96);
    int kLen = (ks == 0) ? 112 : 96;

    const float* A  = Ain + (size_t)bz * sA + kOff;
    const float* Bm = Bin + (size_t)bz * sB + (size_t)kOff * N;
    float*       C  = Cout + (size_t)bz * sC;

    int m0 = blockIdx.y * 64, n0 = blockIdx.x * 32;
    int tid = threadIdx.x;
    int tx = tid & 7;
    int ty = tid >> 3;

    __shared__ float As[2][16][68];
    __shared__ float Bs[2][16][36];

    float acc[2][4] = {};

    int lm  = tid >> 2;
    int lk4 = tid & 3;
    int bkr = tid >> 4;
    int bnc = tid & 15;

    {
        float4 av = make_float4(0.f, 0.f, 0.f, 0.f);
        int gm = m0 + lm;
        if (gm < M) av = *(const float4*)(A + (size_t)gm * Kfull + lk4 * 4);
        As[0][lk4 * 4 + 0][lm] = av.x;
        As[0][lk4 * 4 + 1][lm] = av.y;
        As[0][lk4 * 4 + 2][lm] = av.z;
        As[0][lk4 * 4 + 3][lm] = av.w;
        float2 bv = *(const float2*)(Bm + (size_t)bkr * N + n0 + bnc * 2);
        Bs[0][bkr][bnc * 2 + 0] = bv.x;
        Bs[0][bkr][bnc * 2 + 1] = bv.y;
    }
    __syncthreads();

    int buf = 0;
    for (int k = 0; k < kLen; k += 16) {
        bool hasNext = (k + 16 < kLen);
        float4 av2 = make_float4(0.f, 0.f, 0.f, 0.f);
        float2 bv2 = make_float2(0.f, 0.f);
        if (hasNext) {
            int gm = m0 + lm;
            if (gm < M) av2 = *(const float4*)(A + (size_t)gm * Kfull + k + 16 + lk4 * 4);
            bv2 = *(const float2*)(Bm + (size_t)(k + 16 + bkr) * N + n0 + bnc * 2);
        }
#pragma unroll
        for (int kk = 0; kk < 16; kk++) {
            float2 a = *(float2*)&As[buf][kk][ty * 2];
            float4 b = *(float4*)&Bs[buf][kk][tx * 4];
            acc[0][0] = fmaf(a.x, b.x, acc[0][0]);
            acc[0][1] = fmaf(a.x, b.y, acc[0][1]);
            acc[0][2] = fmaf(a.x, b.z, acc[0][2]);
            acc[0][3] = fmaf(a.x, b.w, acc[0][3]);
            acc[1][0] = fmaf(a.y, b.x, acc[1][0]);
            acc[1][1] = fmaf(a.y, b.y, acc[1][1]);
            acc[1][2] = fmaf(a.y, b.z, acc[1][2]);
            acc[1][3] = fmaf(a.y, b.w, acc[1][3]);
        }
        if (hasNext) {
            int nb = buf ^ 1;
            As[nb][lk4 * 4 + 0][lm] = av2.x;
            As[nb][lk4 * 4 + 1][lm] = av2.y;
            As[nb][lk4 * 4 + 2][lm] = av2.z;
            As[nb][lk4 * 4 + 3][lm] = av2.w;
            Bs[nb][bkr][bnc * 2 + 0] = bv2.x;
            Bs[nb][bkr][bnc * 2 + 1] = bv2.y;
            __syncthreads();
            buf = nb;
        }
    }

#pragma unroll
    for (int i = 0; i < 2; i++) {
        int gm = m0 + ty * 2 + i;
        if (gm < M) {
#pragma unroll
            for (int j = 0; j < 4; j++)
                atomicAdd(&C[(size_t)gm * N + n0 + tx * 4 + j], acc[i][j]);
        }
    }
}

// ---------------------------------------------------------------------------
// attn_pass: PASS2 fuses shifted coverage cumsum in prologue; PASS1 zeroes
// the loss slot AND the ctx output (for gemm_ctx atomics).
// ---------------------------------------------------------------------------
template <bool PASS2>
__global__ __launch_bounds__(NTH, 3) void attn_pass(
    const unsigned char* __restrict__ mask,
    const float* __restrict__ v,
    const float* __restrict__ wc,
    float* __restrict__ AoutParam,
    float* __restrict__ loss,
    float* __restrict__ ctxZero)
{
    __shared__ float2 sVW[H_];        // (v[h], wc[h])
    __shared__ float2 sWp[H_];        // (ws_t0[h], ws_t1[h])
    __shared__ float  sRed[48];

    int tid = threadIdx.x;
    int b   = blockIdx.x / (T_ / TGT);
    int t0  = (blockIdx.x % (T_ / TGT)) * TGT;

    if (!PASS2) {
        // zero ctx: 400 CTAs x 512 floats == B*T*H == 204800 exactly
        size_t base = (size_t)blockIdx.x * 512;
        for (int i = tid; i < 512; i += NTH) ctxZero[base + i] = 0.f;
        if (blockIdx.x == 0 && tid == 0) *loss = 0.f;
    }

    const float* ws0 = g_Ws + ((size_t)b * T_ + t0) * H_;
    for (int h = tid; h < H_; h += NTH) {
        sVW[h] = make_float2(v[h], PASS2 ? wc[h] : 0.f);
        sWp[h] = make_float2(ws0[h], ws0[H_ + h]);
    }
    __syncthreads();

    size_t row0 = ((size_t)b * T_ + t0) * S_;
    size_t row1 = row0 + S_;

    int s = tid;
    float ex0 = 0.f, ex1 = 0.f;
    float c0 = 0.f, c1 = 0.f;
    if (s < S_) {
        const float* whp = g_WhT + (size_t)b * H_ * S_ + s;
        bool mk = mask[b * S_ + s] != 0;

        if (PASS2) {
            // fused shifted cumsum: c0 = sum_{t'<t0} Apre, c1 = c0 + Apre[t0]
            const float* ap = g_Apre + (size_t)b * T_ * S_ + s;
            float sum = 0.f;
            int t = 0;
            for (; t + 4 <= t0; t += 4) {
                float a0 = __ldg(ap + (size_t)t * S_);
                float a1 = __ldg(ap + (size_t)(t + 1) * S_);
                float a2 = __ldg(ap + (size_t)(t + 2) * S_);
                float a3 = __ldg(ap + (size_t)(t + 3) * S_);
                sum += (a0 + a1) + (a2 + a3);
            }
            for (; t < t0; t++) sum += __ldg(ap + (size_t)t * S_);
            c0 = sum;
            c1 = sum + __ldg(ap + (size_t)t0 * S_);
        }

        float acc0 = 0.f, acc1 = 0.f;

        // rotating scalar prefetch, depth 4; branchless tail (clamped index)
        float p0 = __ldg(whp);
        float p1 = __ldg(whp + S_);
        float p2 = __ldg(whp + 2 * S_);
        float p3 = __ldg(whp + 3 * S_);

#pragma unroll 2
        for (int h0 = 0; h0 < H_; h0 += 4) {
            int hn = (h0 + 4 < H_) ? (h0 + 4) : 0;   // SEL, no branch
            const float* q = whp + (size_t)hn * S_;
            float n0 = __ldg(q);
            float n1 = __ldg(q + S_);
            float n2 = __ldg(q + 2 * S_);
            float n3 = __ldg(q + 3 * S_);
#pragma unroll
            for (int i = 0; i < 4; i++) {
                float whv = (i == 0) ? p0 : (i == 1) ? p1 : (i == 2) ? p2 : p3;
                int h = h0 + i;
                float2 vw = sVW[h];
                float2 wp = sWp[h];
                float x0 = whv + wp.x;
                float x1 = whv + wp.y;
                if (PASS2) {
                    x0 = fmaf(c0, vw.y, x0);
                    x1 = fmaf(c1, vw.y, x1);
                }
                __half2 xh = __floats2half2_rn(x0, x1);
                unsigned th = tanh2(*(unsigned*)&xh);
                __half2 t2 = *(__half2*)&th;
                acc0 = fmaf(vw.x, __low2float(t2),  acc0);
                acc1 = fmaf(vw.x, __high2float(t2), acc1);
            }
            p0 = n0; p1 = n1; p2 = n2; p3 = n3;
        }

        float e0 = fminf(fmaxf(acc0, -30.0f), 30.0f);
        float e1 = fminf(fmaxf(acc1, -30.0f), 30.0f);
        // fixed max = 30 (clip upper bound) -> exp in [e^-60, 1], masked -> 0
        ex0 = mk ? 0.f : __expf(e0 - 30.0f);
        ex1 = mk ? 0.f : __expf(e1 - 30.0f);
    }

    // fused dual-sum reduction (2 syncs)
    int lane = tid & 31, wid = tid >> 5;  // 13 warps
    float s0 = ex0, s1 = ex1;
#pragma unroll
    for (int o = 16; o; o >>= 1) {
        s0 += __shfl_xor_sync(0xffffffffu, s0, o);
        s1 += __shfl_xor_sync(0xffffffffu, s1, o);
    }
    if (lane == 0) { sRed[wid] = s0; sRed[16 + wid] = s1; }
    __syncthreads();
    if (wid == 0) {
        float a0 = (lane < 13) ? sRed[lane]      : 0.f;
        float a1 = (lane < 13) ? sRed[16 + lane] : 0.f;
#pragma unroll
        for (int o = 16; o; o >>= 1) {
            a0 += __shfl_xor_sync(0xffffffffu, a0, o);
            a1 += __shfl_xor_sync(0xffffffffu, a1, o);
        }
        if (lane == 0) { sRed[32] = a0; sRed[33] = a1; }
    }
    __syncthreads();
    float inv0 = 1.0f / fmaxf(sRed[32], 1e-30f);
    float inv1 = 1.0f / fmaxf(sRed[33], 1e-30f);

    float lossAcc = 0.f;
    if (s < S_) {
        float a0 = ex0 * inv0;
        float a1 = ex1 * inv1;
        float* out0 = (PASS2 ? AoutParam : g_Apre);
        out0[row0 + s] = a0;
        out0[row1 + s] = a1;
        if (PASS2) lossAcc = fminf(a0, c0) + fminf(a1, c1);
    }

    if (PASS2) {
        __syncthreads();  // protect sRed reuse
#pragma unroll
        for (int o = 16; o; o >>= 1) lossAcc += __shfl_xor_sync(0xffffffffu, lossAcc, o);
        if (lane == 0) sRed[wid] = lossAcc;
        __syncthreads();
        if (tid == 0) {
            float p = 0.f;
#pragma unroll
            for (int i = 0; i < 13; i++) p += sRed[i];
            atomicAdd(loss, p * (1.0f / (B_ * T_)));
        }
    }
}

// ---------------------------------------------------------------------------
extern "C" void kernel_launch(void* const* d_in, const int* in_sizes, int n_in,
                              void* d_out, int out_size)
{
    const float*         dec    = (const float*)d_in[0];
    const float*         enc    = (const float*)d_in[1];
    const unsigned char* mask   = (const unsigned char*)d_in[2];
    const float*         W_h    = (const float*)d_in[3];
    const float*         W_s    = (const float*)d_in[4];
    const float*         w_c    = (const float*)d_in[5];
    const float*         v      = (const float*)d_in[6];
    const float*         b_attn = (const float*)d_in[7];

    float* out  = (float*)d_out;
    float* ctx  = out;
    float* Afin = out + (size_t)B_ * T_ * H_;
    float* loss = Afin + (size_t)B_ * T_ * S_;

    // Fused projections: 50 WhT tiles + 13 Ws tiles -> grid (8, 63)
    dual_gemm<<<dim3(H_ / 32, 63), 256>>>(enc, W_h, dec, W_s, b_attn);

    // Pass 1: A_prelim (also zeroes loss slot + ctx for the atomics)
    attn_pass<false><<<B_ * (T_ / TGT), NTH>>>(mask, v, nullptr, nullptr, loss, ctx);

    // Pass 2: A_final + cov_loss (cumsum fused into prologue)
    attn_pass<true><<<B_ * (T_ / TGT), NTH>>>(mask, v, w_c, Afin, loss, nullptr);

    // context[b] = A_final[b] @ enc[b]  (split-K=4, atomic combine)
    gemm_ctx<<<dim3(H_ / 32, (T_ + 63) / 64, B_ * 4), 256>>>(
        Afin, enc, ctx, T_, H_, S_,
        (long long)T_ * S_, (long long)S_ * H_, (long long)T_ * H_);
}

// round 16
// speedup vs baseline: 1.0355x; 1.0355x over previous
#include <cuda_runtime.h>
#include <cuda_fp16.h>

// Problem dims (fixed by reference setup_inputs)
constexpr int B_ = 8;
constexpr int T_ = 100;
constexpr int S_ = 400;
constexpr int H_ = 256;

constexpr int TGT = 2;    // t-rows per attn CTA
constexpr int NTH = 416;  // attn threads (13 warps; 400 active s-lanes)

// Scratch (device globals — no allocation allowed)
__device__ float g_WhT[B_ * H_ * S_];   // (enc @ W_h + b_attn)^T : [b][h][s]
__device__ float g_Ws [B_ * T_ * H_];   // dec @ W_s
__device__ float g_Apre[B_ * T_ * S_];  // A_prelim

// Scalar single-MUFU tanh; issue-bound loop prefers 2x these over
// pack+tanh.f16x2+unpack (9 vs 11 instr/h, shorter dep chain, full fp32).
__device__ __forceinline__ float fast_tanh(float x) {
    float y;
    asm("tanh.approx.f32 %0, %1;" : "=f"(y) : "f"(x));
    return y;
}

// ---------------------------------------------------------------------------
// Fused projection GEMMs, 64x32 tiles, 256 thr, 2x4 per thread.
// SMEM double-buffered: one __syncthreads per k-chunk, LDG issued early.
// blockIdx.y <  50 : WhT tile -> transposed store into g_WhT (+bias)
// blockIdx.y >= 50 : Ws  tile -> row-major store into g_Ws
// ---------------------------------------------------------------------------
__global__ __launch_bounds__(256) void dual_gemm(
    const float* __restrict__ enc, const float* __restrict__ W_h,
    const float* __restrict__ dec, const float* __restrict__ W_s,
    const float* __restrict__ bias)
{
    constexpr int K = H_, N = H_;
    bool isWh = blockIdx.y < 50;
    int  myTile = isWh ? blockIdx.y : (blockIdx.y - 50);
    int  M  = isWh ? B_ * S_ : B_ * T_;
    const float* A  = isWh ? enc : dec;
    const float* Bm = isWh ? W_h : W_s;

    int m0 = myTile * 64, n0 = blockIdx.x * 32;
    int tid = threadIdx.x;
    int tx = tid & 7;
    int ty = tid >> 3;

    __shared__ float As[2][16][68];
    __shared__ float Bs[2][16][36];
    __shared__ float Ts[32][65];

    float acc[2][4] = {};

    int lm  = tid >> 2;
    int lk4 = tid & 3;
    int bkr = tid >> 4;
    int bnc = tid & 15;

    // prologue: chunk 0 -> buffer 0
    {
        float4 av = make_float4(0.f, 0.f, 0.f, 0.f);
        int gm = m0 + lm;
        if (gm < M) av = *(const float4*)(A + (size_t)gm * K + lk4 * 4);
        As[0][lk4 * 4 + 0][lm] = av.x;
        As[0][lk4 * 4 + 1][lm] = av.y;
        As[0][lk4 * 4 + 2][lm] = av.z;
        As[0][lk4 * 4 + 3][lm] = av.w;
        float2 bv = *(const float2*)(Bm + (size_t)bkr * N + n0 + bnc * 2);
        Bs[0][bkr][bnc * 2 + 0] = bv.x;
        Bs[0][bkr][bnc * 2 + 1] = bv.y;
    }
    __syncthreads();

    int buf = 0;
    for (int k = 0; k < K; k += 16) {
        bool hasNext = (k + 16 < K);
        float4 av2 = make_float4(0.f, 0.f, 0.f, 0.f);
        float2 bv2 = make_float2(0.f, 0.f);
        if (hasNext) {
            int gm = m0 + lm;
            if (gm < M) av2 = *(const float4*)(A + (size_t)gm * K + k + 16 + lk4 * 4);
            bv2 = *(const float2*)(Bm + (size_t)(k + 16 + bkr) * N + n0 + bnc * 2);
        }
#pragma unroll
        for (int kk = 0; kk < 16; kk++) {
            float2 a = *(float2*)&As[buf][kk][ty * 2];
            float4 b = *(float4*)&Bs[buf][kk][tx * 4];
            acc[0][0] = fmaf(a.x, b.x, acc[0][0]);
            acc[0][1] = fmaf(a.x, b.y, acc[0][1]);
            acc[0][2] = fmaf(a.x, b.z, acc[0][2]);
            acc[0][3] = fmaf(a.x, b.w, acc[0][3]);
            acc[1][0] = fmaf(a.y, b.x, acc[1][0]);
            acc[1][1] = fmaf(a.y, b.y, acc[1][1]);
            acc[1][2] = fmaf(a.y, b.z, acc[1][2]);
            acc[1][3] = fmaf(a.y, b.w, acc[1][3]);
        }
        if (hasNext) {
            int nb = buf ^ 1;
            As[nb][lk4 * 4 + 0][lm] = av2.x;
            As[nb][lk4 * 4 + 1][lm] = av2.y;
            As[nb][lk4 * 4 + 2][lm] = av2.z;
            As[nb][lk4 * 4 + 3][lm] = av2.w;
            Bs[nb][bkr][bnc * 2 + 0] = bv2.x;
            Bs[nb][bkr][bnc * 2 + 1] = bv2.y;
            __syncthreads();
            buf = nb;
        }
    }

    if (isWh) {
        __syncthreads();  // protect Ts vs in-flight As/Bs reads
#pragma unroll
        for (int j = 0; j < 4; j++) {
            float bi = bias[n0 + tx * 4 + j];
#pragma unroll
            for (int i = 0; i < 2; i++)
                Ts[tx * 4 + j][ty * 2 + i] = acc[i][j] + bi;
        }
        __syncthreads();
#pragma unroll
        for (int kk = 0; kk < 8; kk++) {
            int e  = tid + 256 * kk;
            int h  = e >> 6;
            int sl = e & 63;
            int m  = m0 + sl;
            int b  = m / S_;
            int s  = m - b * S_;
            g_WhT[(size_t)b * H_ * S_ + (size_t)(n0 + h) * S_ + s] = Ts[h][sl];
        }
    } else {
#pragma unroll
        for (int i = 0; i < 2; i++) {
            int gm = m0 + ty * 2 + i;
            if (gm < M) {
#pragma unroll
                for (int j = 0; j < 4; j++)
                    g_Ws[(size_t)gm * N + n0 + tx * 4 + j] = acc[i][j];
            }
        }
    }
}

// ---------------------------------------------------------------------------
// Context GEMM, split-K(8): blockIdx.z = b*8 + ks. K slices 64 + 7x48.
// 64x32 tiles, 2x4 per thread, double-buffered; partials combined via
// atomicAdd (ctx is zeroed by attn_pass<false>).
// ---------------------------------------------------------------------------
__global__ __launch_bounds__(256) void gemm_ctx(
    const float* __restrict__ Ain, const float* __restrict__ Bin,
    float* __restrict__ Cout, int M, int N, int Kfull,
    long long sA, long long sB, long long sC)
{
    int bz = blockIdx.z >> 3;
    int ks = blockIdx.z & 7;
    int kOff = ks ? (64 + (ks - 1) * 48) : 0;
    int kLen = ks ? 48 : 64;

    const float* A  = Ain + (size_t)bz * sA + kOff;
    const float* Bm = Bin + (size_t)bz * sB + (size_t)kOff * N;
    float*       C  = Cout + (size_t)bz * sC;

    int m0 = blockIdx.y * 64, n0 = blockIdx.x * 32;
    int tid = threadIdx.x;
    int tx = tid & 7;
    int ty = tid >> 3;

    __shared__ float As[2][16][68];
    __shared__ float Bs[2][16][36];

    float acc[2][4] = {};

    int lm  = tid >> 2;
    int lk4 = tid & 3;
    int bkr = tid >> 4;
    int bnc = tid & 15;

    {
        float4 av = make_float4(0.f, 0.f, 0.f, 0.f);
        int gm = m0 + lm;
        if (gm < M) av = *(const float4*)(A + (size_t)gm * Kfull + lk4 * 4);
        As[0][lk4 * 4 + 0][lm] = av.x;
        As[0][lk4 * 4 + 1][lm] = av.y;
        As[0][lk4 * 4 + 2][lm] = av.z;
        As[0][lk4 * 4 + 3][lm] = av.w;
        float2 bv = *(const float2*)(Bm + (size_t)bkr * N + n0 + bnc * 2);
        Bs[0][bkr][bnc * 2 + 0] = bv.x;
        Bs[0][bkr][bnc * 2 + 1] = bv.y;
    }
    __syncthreads();

    int buf = 0;
    for (int k = 0; k < kLen; k += 16) {
        bool hasNext = (k + 16 < kLen);
        float4 av2 = make_float4(0.f, 0.f, 0.f, 0.f);
        float2 bv2 = make_float2(0.f, 0.f);
        if (hasNext) {
            int gm = m0 + lm;
            if (gm < M) av2 = *(const float4*)(A + (size_t)gm * Kfull + k + 16 + lk4 * 4);
            bv2 = *(const float2*)(Bm + (size_t)(k + 16 + bkr) * N + n0 + bnc * 2);
        }
#pragma unroll
        for (int kk = 0; kk < 16; kk++) {
            float2 a = *(float2*)&As[buf][kk][ty * 2];
            float4 b = *(float4*)&Bs[buf][kk][tx * 4];
            acc[0][0] = fmaf(a.x, b.x, acc[0][0]);
            acc[0][1] = fmaf(a.x, b.y, acc[0][1]);
            acc[0][2] = fmaf(a.x, b.z, acc[0][2]);
            acc[0][3] = fmaf(a.x, b.w, acc[0][3]);
            acc[1][0] = fmaf(a.y, b.x, acc[1][0]);
            acc[1][1] = fmaf(a.y, b.y, acc[1][1]);
            acc[1][2] = fmaf(a.y, b.z, acc[1][2]);
            acc[1][3] = fmaf(a.y, b.w, acc[1][3]);
        }
        if (hasNext) {
            int nb = buf ^ 1;
            As[nb][lk4 * 4 + 0][lm] = av2.x;
            As[nb][lk4 * 4 + 1][lm] = av2.y;
            As[nb][lk4 * 4 + 2][lm] = av2.z;
            As[nb][lk4 * 4 + 3][lm] = av2.w;
            Bs[nb][bkr][bnc * 2 + 0] = bv2.x;
            Bs[nb][bkr][bnc * 2 + 1] = bv2.y;
            __syncthreads();
            buf = nb;
        }
    }

#pragma unroll
    for (int i = 0; i < 2; i++) {
        int gm = m0 + ty * 2 + i;
        if (gm < M) {
#pragma unroll
            for (int j = 0; j < 4; j++)
                atomicAdd(&C[(size_t)gm * N + n0 + tx * 4 + j], acc[i][j]);
        }
    }
}

// ---------------------------------------------------------------------------
// attn_pass: PASS2 fuses shifted coverage cumsum in prologue; PASS1 zeroes
// the loss slot AND the ctx output (for gemm_ctx atomics). f32 tanh.
// ---------------------------------------------------------------------------
template <bool PASS2>
__global__ __launch_bounds__(NTH, 3) void attn_pass(
    const unsigned char* __restrict__ mask,
    const float* __restrict__ v,
    const float* __restrict__ wc,
    float* __restrict__ AoutParam,
    float* __restrict__ loss,
    float* __restrict__ ctxZero)
{
    __shared__ float2 sVW[H_];        // (v[h], wc[h])
    __shared__ float2 sWp[H_];        // (ws_t0[h], ws_t1[h])
    __shared__ float  sRed[48];

    int tid = threadIdx.x;
    int b   = blockIdx.x / (T_ / TGT);
    int t0  = (blockIdx.x % (T_ / TGT)) * TGT;

    if (!PASS2) {
        // zero ctx: 400 CTAs x 512 floats == B*T*H == 204800 exactly
        size_t base = (size_t)blockIdx.x * 512;
        for (int i = tid; i < 512; i += NTH) ctxZero[base + i] = 0.f;
        if (blockIdx.x == 0 && tid == 0) *loss = 0.f;
    }

    const float* ws0 = g_Ws + ((size_t)b * T_ + t0) * H_;
    for (int h = tid; h < H_; h += NTH) {
        sVW[h] = make_float2(v[h], PASS2 ? wc[h] : 0.f);
        sWp[h] = make_float2(ws0[h], ws0[H_ + h]);
    }
    __syncthreads();

    size_t row0 = ((size_t)b * T_ + t0) * S_;
    size_t row1 = row0 + S_;

    int s = tid;
    float ex0 = 0.f, ex1 = 0.f;
    float c0 = 0.f, c1 = 0.f;
    if (s < S_) {
        const float* whp = g_WhT + (size_t)b * H_ * S_ + s;
        bool mk = mask[b * S_ + s] != 0;

        if (PASS2) {
            // fused shifted cumsum: c0 = sum_{t'<t0} Apre, c1 = c0 + Apre[t0]
            const float* ap = g_Apre + (size_t)b * T_ * S_ + s;
            float sum = 0.f;
            int t = 0;
            for (; t + 4 <= t0; t += 4) {
                float a0 = __ldg(ap + (size_t)t * S_);
                float a1 = __ldg(ap + (size_t)(t + 1) * S_);
                float a2 = __ldg(ap + (size_t)(t + 2) * S_);
                float a3 = __ldg(ap + (size_t)(t + 3) * S_);
                sum += (a0 + a1) + (a2 + a3);
            }
            for (; t < t0; t++) sum += __ldg(ap + (size_t)t * S_);
            c0 = sum;
            c1 = sum + __ldg(ap + (size_t)t0 * S_);
        }

        float acc0 = 0.f, acc1 = 0.f;

        // rotating scalar prefetch, depth 4; branchless tail (clamped index)
        float p0 = __ldg(whp);
        float p1 = __ldg(whp + S_);
        float p2 = __ldg(whp + 2 * S_);
        float p3 = __ldg(whp + 3 * S_);

#pragma unroll 2
        for (int h0 = 0; h0 < H_; h0 += 4) {
            int hn = (h0 + 4 < H_) ? (h0 + 4) : 0;   // SEL, no branch
            const float* q = whp + (size_t)hn * S_;
            float n0 = __ldg(q);
            float n1 = __ldg(q + S_);
            float n2 = __ldg(q + 2 * S_);
            float n3 = __ldg(q + 3 * S_);
#pragma unroll
            for (int i = 0; i < 4; i++) {
                float whv = (i == 0) ? p0 : (i == 1) ? p1 : (i == 2) ? p2 : p3;
                int h = h0 + i;
                float2 vw = sVW[h];
                float2 wp = sWp[h];
                float x0 = whv + wp.x;
                float x1 = whv + wp.y;
                if (PASS2) {
                    x0 = fmaf(c0, vw.y, x0);
                    x1 = fmaf(c1, vw.y, x1);
                }
                acc0 = fmaf(vw.x, fast_tanh(x0), acc0);
                acc1 = fmaf(vw.x, fast_tanh(x1), acc1);
            }
            p0 = n0; p1 = n1; p2 = n2; p3 = n3;
        }

        float e0 = fminf(fmaxf(acc0, -30.0f), 30.0f);
        float e1 = fminf(fmaxf(acc1, -30.0f), 30.0f);
        // fixed max = 30 (clip upper bound) -> exp in [e^-60, 1], masked -> 0
        ex0 = mk ? 0.f : __expf(e0 - 30.0f);
        ex1 = mk ? 0.f : __expf(e1 - 30.0f);
    }

    // fused dual-sum reduction (2 syncs)
    int lane = tid & 31, wid = tid >> 5;  // 13 warps
    float s0 = ex0, s1 = ex1;
#pragma unroll
    for (int o = 16; o; o >>= 1) {
        s0 += __shfl_xor_sync(0xffffffffu, s0, o);
        s1 += __shfl_xor_sync(0xffffffffu, s1, o);
    }
    if (lane == 0) { sRed[wid] = s0; sRed[16 + wid] = s1; }
    __syncthreads();
    if (wid == 0) {
        float a0 = (lane < 13) ? sRed[lane]      : 0.f;
        float a1 = (lane < 13) ? sRed[16 + lane] : 0.f;
#pragma unroll
        for (int o = 16; o; o >>= 1) {
            a0 += __shfl_xor_sync(0xffffffffu, a0, o);
            a1 += __shfl_xor_sync(0xffffffffu, a1, o);
        }
        if (lane == 0) { sRed[32] = a0; sRed[33] = a1; }
    }
    __syncthreads();
    float inv0 = 1.0f / fmaxf(sRed[32], 1e-30f);
    float inv1 = 1.0f / fmaxf(sRed[33], 1e-30f);

    float lossAcc = 0.f;
    if (s < S_) {
        float a0 = ex0 * inv0;
        float a1 = ex1 * inv1;
        float* out0 = (PASS2 ? AoutParam : g_Apre);
        out0[row0 + s] = a0;
        out0[row1 + s] = a1;
        if (PASS2) lossAcc = fminf(a0, c0) + fminf(a1, c1);
    }

    if (PASS2) {
        __syncthreads();  // protect sRed reuse
#pragma unroll
        for (int o = 16; o; o >>= 1) lossAcc += __shfl_xor_sync(0xffffffffu, lossAcc, o);
        if (lane == 0) sRed[wid] = lossAcc;
        __syncthreads();
        if (tid == 0) {
            float p = 0.f;
#pragma unroll
            for (int i = 0; i < 13; i++) p += sRed[i];
            atomicAdd(loss, p * (1.0f / (B_ * T_)));
        }
    }
}

// ---------------------------------------------------------------------------
extern "C" void kernel_launch(void* const* d_in, const int* in_sizes, int n_in,
                              void* d_out, int out_size)
{
    const float*         dec    = (const float*)d_in[0];
    const float*         enc    = (const float*)d_in[1];
    const unsigned char* mask   = (const unsigned char*)d_in[2];
    const float*         W_h    = (const float*)d_in[3];
    const float*         W_s    = (const float*)d_in[4];
    const float*         w_c    = (const float*)d_in[5];
    const float*         v      = (const float*)d_in[6];
    const float*         b_attn = (const float*)d_in[7];

    float* out  = (float*)d_out;
    float* ctx  = out;
    float* Afin = out + (size_t)B_ * T_ * H_;
    float* loss = Afin + (size_t)B_ * T_ * S_;

    // Fused projections: 50 WhT tiles + 13 Ws tiles -> grid (8, 63)
    dual_gemm<<<dim3(H_ / 32, 63), 256>>>(enc, W_h, dec, W_s, b_attn);

    // Pass 1: A_prelim (also zeroes loss slot + ctx for the atomics)
    attn_pass<false><<<B_ * (T_ / TGT), NTH>>>(mask, v, nullptr, nullptr, loss, ctx);

    // Pass 2: A_final + cov_loss (cumsum fused into prologue)
    attn_pass<true><<<B_ * (T_ / TGT), NTH>>>(mask, v, w_c, Afin, loss, nullptr);

    // context[b] = A_final[b] @ enc[b]  (split-K=8, atomic combine)
    gemm_ctx<<<dim3(H_ / 32, (T_ + 63) / 64, B_ * 8), 256>>>(
        Afin, enc, ctx, T_, H_, S_,
        (long long)T_ * S_, (long long)S_ * H_, (long long)T_ * H_);
}

// round 17
// speedup vs baseline: 1.0653x; 1.0288x over previous
#include <cuda_runtime.h>
#include <cuda_fp16.h>

// Problem dims (fixed by reference setup_inputs)
constexpr int B_ = 8;
constexpr int T_ = 100;
constexpr int S_ = 400;
constexpr int H_ = 256;

constexpr int TGT = 2;    // t-rows per attn CTA
constexpr int NTH = 416;  // attn threads (13 warps; 400 active s-lanes)

// Scratch (device globals — no allocation allowed)
__device__ float g_WhT[B_ * H_ * S_];   // (enc @ W_h + b_attn)^T : [b][h][s]
__device__ float g_Ws [B_ * T_ * H_];   // dec @ W_s
__device__ float g_Apre[B_ * T_ * S_];  // A_prelim

// Scalar single-MUFU tanh (full fp32; proven faster than f16x2 pack path).
__device__ __forceinline__ float fast_tanh(float x) {
    float y;
    asm("tanh.approx.f32 %0, %1;" : "=f"(y) : "f"(x));
    return y;
}

// ---------------------------------------------------------------------------
// Fused projection GEMMs, 64x32 tiles, 256 thr, 2x4 per thread.
// SMEM double-buffered: one __syncthreads per k-chunk, LDG issued early.
// blockIdx.y <  50 : WhT tile -> transposed store into g_WhT (+bias)
// blockIdx.y >= 50 : Ws  tile -> row-major store into g_Ws
// ---------------------------------------------------------------------------
__global__ __launch_bounds__(256) void dual_gemm(
    const float* __restrict__ enc, const float* __restrict__ W_h,
    const float* __restrict__ dec, const float* __restrict__ W_s,
    const float* __restrict__ bias)
{
    constexpr int K = H_, N = H_;
    bool isWh = blockIdx.y < 50;
    int  myTile = isWh ? blockIdx.y : (blockIdx.y - 50);
    int  M  = isWh ? B_ * S_ : B_ * T_;
    const float* A  = isWh ? enc : dec;
    const float* Bm = isWh ? W_h : W_s;

    int m0 = myTile * 64, n0 = blockIdx.x * 32;
    int tid = threadIdx.x;
    int tx = tid & 7;
    int ty = tid >> 3;

    __shared__ float As[2][16][68];
    __shared__ float Bs[2][16][36];
    __shared__ float Ts[32][65];

    float acc[2][4] = {};

    int lm  = tid >> 2;
    int lk4 = tid & 3;
    int bkr = tid >> 4;
    int bnc = tid & 15;

    // prologue: chunk 0 -> buffer 0
    {
        float4 av = make_float4(0.f, 0.f, 0.f, 0.f);
        int gm = m0 + lm;
        if (gm < M) av = *(const float4*)(A + (size_t)gm * K + lk4 * 4);
        As[0][lk4 * 4 + 0][lm] = av.x;
        As[0][lk4 * 4 + 1][lm] = av.y;
        As[0][lk4 * 4 + 2][lm] = av.z;
        As[0][lk4 * 4 + 3][lm] = av.w;
        float2 bv = *(const float2*)(Bm + (size_t)bkr * N + n0 + bnc * 2);
        Bs[0][bkr][bnc * 2 + 0] = bv.x;
        Bs[0][bkr][bnc * 2 + 1] = bv.y;
    }
    __syncthreads();

    int buf = 0;
    for (int k = 0; k < K; k += 16) {
        bool hasNext = (k + 16 < K);
        float4 av2 = make_float4(0.f, 0.f, 0.f, 0.f);
        float2 bv2 = make_float2(0.f, 0.f);
        if (hasNext) {
            int gm = m0 + lm;
            if (gm < M) av2 = *(const float4*)(A + (size_t)gm * K + k + 16 + lk4 * 4);
            bv2 = *(const float2*)(Bm + (size_t)(k + 16 + bkr) * N + n0 + bnc * 2);
        }
#pragma unroll
        for (int kk = 0; kk < 16; kk++) {
            float2 a = *(float2*)&As[buf][kk][ty * 2];
            float4 b = *(float4*)&Bs[buf][kk][tx * 4];
            acc[0][0] = fmaf(a.x, b.x, acc[0][0]);
            acc[0][1] = fmaf(a.x, b.y, acc[0][1]);
            acc[0][2] = fmaf(a.x, b.z, acc[0][2]);
            acc[0][3] = fmaf(a.x, b.w, acc[0][3]);
            acc[1][0] = fmaf(a.y, b.x, acc[1][0]);
            acc[1][1] = fmaf(a.y, b.y, acc[1][1]);
            acc[1][2] = fmaf(a.y, b.z, acc[1][2]);
            acc[1][3] = fmaf(a.y, b.w, acc[1][3]);
        }
        if (hasNext) {
            int nb = buf ^ 1;
            As[nb][lk4 * 4 + 0][lm] = av2.x;
            As[nb][lk4 * 4 + 1][lm] = av2.y;
            As[nb][lk4 * 4 + 2][lm] = av2.z;
            As[nb][lk4 * 4 + 3][lm] = av2.w;
            Bs[nb][bkr][bnc * 2 + 0] = bv2.x;
            Bs[nb][bkr][bnc * 2 + 1] = bv2.y;
            __syncthreads();
            buf = nb;
        }
    }

    if (isWh) {
        __syncthreads();  // protect Ts vs in-flight As/Bs reads
#pragma unroll
        for (int j = 0; j < 4; j++) {
            float bi = bias[n0 + tx * 4 + j];
#pragma unroll
            for (int i = 0; i < 2; i++)
                Ts[tx * 4 + j][ty * 2 + i] = acc[i][j] + bi;
        }
        __syncthreads();
#pragma unroll
        for (int kk = 0; kk < 8; kk++) {
            int e  = tid + 256 * kk;
            int h  = e >> 6;
            int sl = e & 63;
            int m  = m0 + sl;
            int b  = m / S_;
            int s  = m - b * S_;
            g_WhT[(size_t)b * H_ * S_ + (size_t)(n0 + h) * S_ + s] = Ts[h][sl];
        }
    } else {
#pragma unroll
        for (int i = 0; i < 2; i++) {
            int gm = m0 + ty * 2 + i;
            if (gm < M) {
#pragma unroll
                for (int j = 0; j < 4; j++)
                    g_Ws[(size_t)gm * N + n0 + tx * 4 + j] = acc[i][j];
            }
        }
    }
}

// ---------------------------------------------------------------------------
// Context GEMM v2: split-K(8), 64x32 tiles, 128 threads, 4x4 per thread
// (2 LDS.128 per 16 FMA -> halves L1 pressure vs 2x4). Double-buffered.
// Partials combined via atomicAdd (ctx zeroed by attn_pass<false>).
// ---------------------------------------------------------------------------
__global__ __launch_bounds__(128) void gemm_ctx(
    const float* __restrict__ Ain, const float* __restrict__ Bin,
    float* __restrict__ Cout, int M, int N, int Kfull,
    long long sA, long long sB, long long sC)
{
    int bz = blockIdx.z >> 3;
    int ks = blockIdx.z & 7;
    int kOff = ks ? (64 + (ks - 1) * 48) : 0;
    int kLen = ks ? 48 : 64;

    const float* A  = Ain + (size_t)bz * sA + kOff;
    const float* Bm = Bin + (size_t)bz * sB + (size_t)kOff * N;
    float*       C  = Cout + (size_t)bz * sC;

    int m0 = blockIdx.y * 64, n0 = blockIdx.x * 32;
    int tid = threadIdx.x;
    int tx = tid & 7;        // 8 col groups of 4
    int ty = tid >> 3;       // 16 row groups of 4

    __shared__ float As[2][16][68];   // [k][m]
    __shared__ float Bs[2][16][36];   // [k][n]

    float acc[4][4] = {};

    // A loaders: 128 thr x 2 float4 = 16k x 64m
    int lm  = tid >> 1;        // 0..63
    int lk8 = (tid & 1) * 8;   // 0 or 8
    // B loaders: 128 thr x 1 float4 = 16k x 32n
    int bkr = tid >> 3;        // 0..15
    int bnc = tid & 7;         // 8 groups of 4

    {
        float4 a0v = make_float4(0.f, 0.f, 0.f, 0.f);
        float4 a1v = a0v;
        int gm = m0 + lm;
        if (gm < M) {
            a0v = *(const float4*)(A + (size_t)gm * Kfull + lk8);
            a1v = *(const float4*)(A + (size_t)gm * Kfull + lk8 + 4);
        }
        As[0][lk8 + 0][lm] = a0v.x;
        As[0][lk8 + 1][lm] = a0v.y;
        As[0][lk8 + 2][lm] = a0v.z;
        As[0][lk8 + 3][lm] = a0v.w;
        As[0][lk8 + 4][lm] = a1v.x;
        As[0][lk8 + 5][lm] = a1v.y;
        As[0][lk8 + 6][lm] = a1v.z;
        As[0][lk8 + 7][lm] = a1v.w;
        float4 bv = *(const float4*)(Bm + (size_t)bkr * N + n0 + bnc * 4);
        *(float4*)&Bs[0][bkr][bnc * 4] = bv;
    }
    __syncthreads();

    int buf = 0;
    for (int k = 0; k < kLen; k += 16) {
        bool hasNext = (k + 16 < kLen);
        float4 a0v = make_float4(0.f, 0.f, 0.f, 0.f);
        float4 a1v = a0v;
        float4 bv2 = a0v;
        if (hasNext) {
            int gm = m0 + lm;
            if (gm < M) {
                a0v = *(const float4*)(A + (size_t)gm * Kfull + k + 16 + lk8);
                a1v = *(const float4*)(A + (size_t)gm * Kfull + k + 16 + lk8 + 4);
            }
            bv2 = *(const float4*)(Bm + (size_t)(k + 16 + bkr) * N + n0 + bnc * 4);
        }
#pragma unroll
        for (int kk = 0; kk < 16; kk++) {
            float4 a = *(float4*)&As[buf][kk][ty * 4];
            float4 b = *(float4*)&Bs[buf][kk][tx * 4];
            acc[0][0] = fmaf(a.x, b.x, acc[0][0]);
            acc[0][1] = fmaf(a.x, b.y, acc[0][1]);
            acc[0][2] = fmaf(a.x, b.z, acc[0][2]);
            acc[0][3] = fmaf(a.x, b.w, acc[0][3]);
            acc[1][0] = fmaf(a.y, b.x, acc[1][0]);
            acc[1][1] = fmaf(a.y, b.y, acc[1][1]);
            acc[1][2] = fmaf(a.y, b.z, acc[1][2]);
            acc[1][3] = fmaf(a.y, b.w, acc[1][3]);
            acc[2][0] = fmaf(a.z, b.x, acc[2][0]);
            acc[2][1] = fmaf(a.z, b.y, acc[2][1]);
            acc[2][2] = fmaf(a.z, b.z, acc[2][2]);
            acc[2][3] = fmaf(a.z, b.w, acc[2][3]);
            acc[3][0] = fmaf(a.w, b.x, acc[3][0]);
            acc[3][1] = fmaf(a.w, b.y, acc[3][1]);
            acc[3][2] = fmaf(a.w, b.z, acc[3][2]);
            acc[3][3] = fmaf(a.w, b.w, acc[3][3]);
        }
        if (hasNext) {
            int nb = buf ^ 1;
            As[nb][lk8 + 0][lm] = a0v.x;
            As[nb][lk8 + 1][lm] = a0v.y;
            As[nb][lk8 + 2][lm] = a0v.z;
            As[nb][lk8 + 3][lm] = a0v.w;
            As[nb][lk8 + 4][lm] = a1v.x;
            As[nb][lk8 + 5][lm] = a1v.y;
            As[nb][lk8 + 6][lm] = a1v.z;
            As[nb][lk8 + 7][lm] = a1v.w;
            *(float4*)&Bs[nb][bkr][bnc * 4] = bv2;
            __syncthreads();
            buf = nb;
        }
    }

#pragma unroll
    for (int i = 0; i < 4; i++) {
        int gm = m0 + ty * 4 + i;
        if (gm < M) {
#pragma unroll
            for (int j = 0; j < 4; j++)
                atomicAdd(&C[(size_t)gm * N + n0 + tx * 4 + j], acc[i][j]);
        }
    }
}

// ---------------------------------------------------------------------------
// attn_pass: PASS2 fuses shifted coverage cumsum in prologue; PASS1 zeroes
// the loss slot AND the ctx output (for gemm_ctx atomics). f32 tanh.
// ---------------------------------------------------------------------------
template <bool PASS2>
__global__ __launch_bounds__(NTH, 3) void attn_pass(
    const unsigned char* __restrict__ mask,
    const float* __restrict__ v,
    const float* __restrict__ wc,
    float* __restrict__ AoutParam,
    float* __restrict__ loss,
    float* __restrict__ ctxZero)
{
    __shared__ float2 sVW[H_];        // (v[h], wc[h])
    __shared__ float2 sWp[H_];        // (ws_t0[h], ws_t1[h])
    __shared__ float  sRed[48];

    int tid = threadIdx.x;
    int b   = blockIdx.x / (T_ / TGT);
    int t0  = (blockIdx.x % (T_ / TGT)) * TGT;

    if (!PASS2) {
        // zero ctx: 400 CTAs x 512 floats == B*T*H == 204800 exactly
        size_t base = (size_t)blockIdx.x * 512;
        for (int i = tid; i < 512; i += NTH) ctxZero[base + i] = 0.f;
        if (blockIdx.x == 0 && tid == 0) *loss = 0.f;
    }

    const float* ws0 = g_Ws + ((size_t)b * T_ + t0) * H_;
    for (int h = tid; h < H_; h += NTH) {
        sVW[h] = make_float2(v[h], PASS2 ? wc[h] : 0.f);
        sWp[h] = make_float2(ws0[h], ws0[H_ + h]);
    }
    __syncthreads();

    size_t row0 = ((size_t)b * T_ + t0) * S_;
    size_t row1 = row0 + S_;

    int s = tid;
    float ex0 = 0.f, ex1 = 0.f;
    float c0 = 0.f, c1 = 0.f;
    if (s < S_) {
        const float* whp = g_WhT + (size_t)b * H_ * S_ + s;
        bool mk = mask[b * S_ + s] != 0;

        if (PASS2) {
            // fused shifted cumsum: c0 = sum_{t'<t0} Apre, c1 = c0 + Apre[t0]
            const float* ap = g_Apre + (size_t)b * T_ * S_ + s;
            float sum = 0.f;
            int t = 0;
            for (; t + 4 <= t0; t += 4) {
                float a0 = __ldg(ap + (size_t)t * S_);
                float a1 = __ldg(ap + (size_t)(t + 1) * S_);
                float a2 = __ldg(ap + (size_t)(t + 2) * S_);
                float a3 = __ldg(ap + (size_t)(t + 3) * S_);
                sum += (a0 + a1) + (a2 + a3);
            }
            for (; t < t0; t++) sum += __ldg(ap + (size_t)t * S_);
            c0 = sum;
            c1 = sum + __ldg(ap + (size_t)t0 * S_);
        }

        float acc0 = 0.f, acc1 = 0.f;

        // rotating scalar prefetch, depth 4; branchless tail (clamped index)
        float p0 = __ldg(whp);
        float p1 = __ldg(whp + S_);
        float p2 = __ldg(whp + 2 * S_);
        float p3 = __ldg(whp + 3 * S_);

#pragma unroll 2
        for (int h0 = 0; h0 < H_; h0 += 4) {
            int hn = (h0 + 4 < H_) ? (h0 + 4) : 0;   // SEL, no branch
            const float* q = whp + (size_t)hn * S_;
            float n0 = __ldg(q);
            float n1 = __ldg(q + S_);
            float n2 = __ldg(q + 2 * S_);
            float n3 = __ldg(q + 3 * S_);
#pragma unroll
            for (int i = 0; i < 4; i++) {
                float whv = (i == 0) ? p0 : (i == 1) ? p1 : (i == 2) ? p2 : p3;
                int h = h0 + i;
                float2 vw = sVW[h];
                float2 wp = sWp[h];
                float x0 = whv + wp.x;
                float x1 = whv + wp.y;
                if (PASS2) {
                    x0 = fmaf(c0, vw.y, x0);
                    x1 = fmaf(c1, vw.y, x1);
                }
                acc0 = fmaf(vw.x, fast_tanh(x0), acc0);
                acc1 = fmaf(vw.x, fast_tanh(x1), acc1);
            }
            p0 = n0; p1 = n1; p2 = n2; p3 = n3;
        }

        float e0 = fminf(fmaxf(acc0, -30.0f), 30.0f);
        float e1 = fminf(fmaxf(acc1, -30.0f), 30.0f);
        // fixed max = 30 (clip upper bound) -> exp in [e^-60, 1], masked -> 0
        ex0 = mk ? 0.f : __expf(e0 - 30.0f);
        ex1 = mk ? 0.f : __expf(e1 - 30.0f);
    }

    // fused dual-sum reduction (2 syncs)
    int lane = tid & 31, wid = tid >> 5;  // 13 warps
    float s0 = ex0, s1 = ex1;
#pragma unroll
    for (int o = 16; o; o >>= 1) {
        s0 += __shfl_xor_sync(0xffffffffu, s0, o);
        s1 += __shfl_xor_sync(0xffffffffu, s1, o);
    }
    if (lane == 0) { sRed[wid] = s0; sRed[16 + wid] = s1; }
    __syncthreads();
    if (wid == 0) {
        float a0 = (lane < 13) ? sRed[lane]      : 0.f;
        float a1 = (lane < 13) ? sRed[16 + lane] : 0.f;
#pragma unroll
        for (int o = 16; o; o >>= 1) {
            a0 += __shfl_xor_sync(0xffffffffu, a0, o);
            a1 += __shfl_xor_sync(0xffffffffu, a1, o);
        }
        if (lane == 0) { sRed[32] = a0; sRed[33] = a1; }
    }
    __syncthreads();
    float inv0 = 1.0f / fmaxf(sRed[32], 1e-30f);
    float inv1 = 1.0f / fmaxf(sRed[33], 1e-30f);

    float lossAcc = 0.f;
    if (s < S_) {
        float a0 = ex0 * inv0;
        float a1 = ex1 * inv1;
        float* out0 = (PASS2 ? AoutParam : g_Apre);
        out0[row0 + s] = a0;
        out0[row1 + s] = a1;
        if (PASS2) lossAcc = fminf(a0, c0) + fminf(a1, c1);
    }

    if (PASS2) {
        __syncthreads();  // protect sRed reuse
#pragma unroll
        for (int o = 16; o; o >>= 1) lossAcc += __shfl_xor_sync(0xffffffffu, lossAcc, o);
        if (lane == 0) sRed[wid] = lossAcc;
        __syncthreads();
        if (tid == 0) {
            float p = 0.f;
#pragma unroll
            for (int i = 0; i < 13; i++) p += sRed[i];
            atomicAdd(loss, p * (1.0f / (B_ * T_)));
        }
    }
}

// ---------------------------------------------------------------------------
extern "C" void kernel_launch(void* const* d_in, const int* in_sizes, int n_in,
                              void* d_out, int out_size)
{
    const float*         dec    = (const float*)d_in[0];
    const float*         enc    = (const float*)d_in[1];
    const unsigned char* mask   = (const unsigned char*)d_in[2];
    const float*         W_h    = (const float*)d_in[3];
    const float*         W_s    = (const float*)d_in[4];
    const float*         w_c    = (const float*)d_in[5];
    const float*         v      = (const float*)d_in[6];
    const float*         b_attn = (const float*)d_in[7];

    float* out  = (float*)d_out;
    float* ctx  = out;
    float* Afin = out + (size_t)B_ * T_ * H_;
    float* loss = Afin + (size_t)B_ * T_ * S_;

    // Fused projections: 50 WhT tiles + 13 Ws tiles -> grid (8, 63)
    dual_gemm<<<dim3(H_ / 32, 63), 256>>>(enc, W_h, dec, W_s, b_attn);

    // Pass 1: A_prelim (also zeroes loss slot + ctx for the atomics)
    attn_pass<false><<<B_ * (T_ / TGT), NTH>>>(mask, v, nullptr, nullptr, loss, ctx);

    // Pass 2: A_final + cov_loss (cumsum fused into prologue)
    attn_pass<true><<<B_ * (T_ / TGT), NTH>>>(mask, v, w_c, Afin, loss, nullptr);

    // context[b] = A_final[b] @ enc[b]  (split-K=8, 4x4 blocking, atomics)
    gemm_ctx<<<dim3(H_ / 32, (T_ + 63) / 64, B_ * 8), 128>>>(
        Afin, enc, ctx, T_, H_, S_,
        (long long)T_ * S_, (long long)S_ * H_, (long long)T_ * H_);
}